// round 5
// baseline (speedup 1.0000x reference)
#include <cuda_runtime.h>
#include <cuda_bf16.h>
#include <cstdint>

#define B_  4
#define L_  2048
#define H_  1024
#define NH_ 16
#define DK_ 64
#define ROWS_ (B_ * L_)          // 8192
#define HEADS_ (B_ * NH_)        // 64

typedef __nv_bfloat16 bf16;

// Q pre-scale: (1/sqrt(64)) * log2(e), so scores are in log2 domain
#define QSCALE 0.18033688011112427f

// ---- scratch (device globals; allocation-free rule) ----
__device__ bf16    g_Xhi[ROWS_ * H_];
__device__ bf16    g_Wqh[H_ * H_];
__device__ bf16    g_Wkh[H_ * H_];
__device__ bf16    g_Qb[ROWS_ * H_];    // row-major, scaled by QSCALE
__device__ bf16    g_Kb[ROWS_ * H_];
__device__ uint8_t g_Q8[ROWS_ * H_];    // e4m3 copies (same values)
__device__ uint8_t g_K8[ROWS_ * H_];
__device__ float   g_cs[HEADS_ * L_];
__device__ float   g_wsum[HEADS_ * H_];
__device__ float   g_ctxmean[B_ * H_];

// ---------------------------------------------------------------------------
// PTX helpers
// ---------------------------------------------------------------------------
__device__ __forceinline__ uint32_t smem_u32(const void* p) {
    return (uint32_t)__cvta_generic_to_shared(p);
}
__device__ __forceinline__ void ldsm_x4(uint32_t& r0, uint32_t& r1, uint32_t& r2,
                                        uint32_t& r3, uint32_t a) {
    asm volatile("ldmatrix.sync.aligned.m8n8.x4.shared.b16 {%0,%1,%2,%3}, [%4];"
                 : "=r"(r0), "=r"(r1), "=r"(r2), "=r"(r3) : "r"(a));
}
__device__ __forceinline__ void ldsm_x2(uint32_t& r0, uint32_t& r1, uint32_t a) {
    asm volatile("ldmatrix.sync.aligned.m8n8.x2.shared.b16 {%0,%1}, [%2];"
                 : "=r"(r0), "=r"(r1) : "r"(a));
}
__device__ __forceinline__ void mma_bf16(float* c, const uint32_t* a, const uint32_t* b) {
    asm volatile("mma.sync.aligned.m16n8k16.row.col.f32.bf16.bf16.f32 "
                 "{%0,%1,%2,%3}, {%4,%5,%6,%7}, {%8,%9}, {%0,%1,%2,%3};"
                 : "+f"(c[0]), "+f"(c[1]), "+f"(c[2]), "+f"(c[3])
                 : "r"(a[0]), "r"(a[1]), "r"(a[2]), "r"(a[3]), "r"(b[0]), "r"(b[1]));
}
__device__ __forceinline__ void mma_fp8(float* c, const uint32_t* a, const uint32_t* b) {
    asm volatile("mma.sync.aligned.m16n8k32.row.col.f32.e4m3.e4m3.f32 "
                 "{%0,%1,%2,%3}, {%4,%5,%6,%7}, {%8,%9}, {%0,%1,%2,%3};"
                 : "+f"(c[0]), "+f"(c[1]), "+f"(c[2]), "+f"(c[3])
                 : "r"(a[0]), "r"(a[1]), "r"(a[2]), "r"(a[3]), "r"(b[0]), "r"(b[1]));
}
__device__ __forceinline__ void cp16(uint32_t dst, const void* src) {
    asm volatile("cp.async.cg.shared.global [%0], [%1], 16;" :: "r"(dst), "l"(src));
}
#define CP_COMMIT()  asm volatile("cp.async.commit_group;" ::: "memory")
#define CP_WAIT0()   asm volatile("cp.async.wait_group 0;" ::: "memory")
#define CP_WAIT1()   asm volatile("cp.async.wait_group 1;" ::: "memory")

__device__ __forceinline__ float ex2f(float x) {
    float y;
    asm("ex2.approx.ftz.f32 %0, %1;" : "=f"(y) : "f"(x));
    return y;
}
__device__ __forceinline__ uint16_t f8pair(float v0, float v1) {
    // low byte = v0, high byte = v1 (pair order irrelevant: consistent Q/K permutation)
    uint16_t r;
    asm("cvt.rn.satfinite.e4m3x2.f32 %0, %1, %2;" : "=h"(r) : "f"(v1), "f"(v0));
    return r;
}

// ---------------------------------------------------------------------------
__global__ void split_k(const float* __restrict__ in, bf16* __restrict__ hi, int n)
{
    int i = blockIdx.x * blockDim.x + threadIdx.x;
    if (i >= n) return;
    hi[i] = __float2bfloat16(in[i]);
}

__global__ void zero_k()
{
    int i = blockIdx.x * blockDim.x + threadIdx.x;
    if (i < HEADS_ * L_) g_cs[i] = 0.f;
    if (i < HEADS_ * H_) g_wsum[i] = 0.f;
}

// ---------------------------------------------------------------------------
// Merged Q/K projection: z=0 -> Q (alpha=QSCALE), z=1 -> K (alpha=1).
// Y = X @ W^T + b, bf16 + e4m3 outputs, row-major. 3-stage cp.async, BK=16.
// ---------------------------------------------------------------------------
__global__ __launch_bounds__(256)
void gemm_qk(const bf16* __restrict__ Xh,
             const bf16* __restrict__ Wqh, const bf16* __restrict__ Wkh,
             const float* __restrict__ bq, const float* __restrict__ bk)
{
    __shared__ bf16 sA[3][128][24];
    __shared__ bf16 sB[3][128][24];

    const int z = blockIdx.z;
    const bf16* Bh = z ? Wkh : Wqh;
    const float* bias = z ? bk : bq;
    const float alpha = z ? 1.0f : QSCALE;
    bf16* outB = z ? g_Kb : g_Qb;
    uint8_t* out8 = z ? g_K8 : g_Q8;

    const int tid = threadIdx.x;
    const int warp = tid >> 5, lane = tid & 31;
    const int wm = warp >> 2, wn = warp & 3;
    const int mbase = wm * 64, nbase = wn * 32;
    const int rowB = blockIdx.y * 128;
    const int colB = blockIdx.x * 128;

    float acc[4][4][4];
#pragma unroll
    for (int i = 0; i < 4; i++)
#pragma unroll
        for (int j = 0; j < 4; j++)
#pragma unroll
            for (int p = 0; p < 4; p++) acc[i][j][p] = 0.f;

    const int lrow = tid >> 1;
    const int lcb  = (tid & 1) * 8;

    auto load_stage = [&](int s, int t) {
        int k0 = t * 16;
        cp16(smem_u32(&sA[s][lrow][lcb]), Xh + (size_t)(rowB + lrow) * H_ + k0 + lcb);
        cp16(smem_u32(&sB[s][lrow][lcb]), Bh + (size_t)(colB + lrow) * H_ + k0 + lcb);
        CP_COMMIT();
    };

    load_stage(0, 0);
    load_stage(1, 1);

    const int T = H_ / 16;   // 64
    for (int t = 0; t < T; t++) {
        if (t + 1 < T) CP_WAIT1(); else CP_WAIT0();
        __syncthreads();
        if (t + 2 < T) load_stage((t + 2) % 3, t + 2);

        const int s = t % 3;
        uint32_t ah[4][4], bh[4][2];
#pragma unroll
        for (int i = 0; i < 4; i++)
            ldsm_x4(ah[i][0], ah[i][1], ah[i][2], ah[i][3],
                    smem_u32(&sA[s][mbase + i * 16 + (lane & 15)][(lane >> 4) * 8]));
#pragma unroll
        for (int j = 0; j < 4; j++)
            ldsm_x2(bh[j][0], bh[j][1],
                    smem_u32(&sB[s][nbase + j * 8 + (lane & 7)][((lane >> 3) & 1) * 8]));
#pragma unroll
        for (int i = 0; i < 4; i++)
#pragma unroll
            for (int j = 0; j < 4; j++)
                mma_bf16(acc[i][j], ah[i], bh[j]);
        __syncthreads();
    }

    const int group = lane >> 2, qd = lane & 3;
#pragma unroll
    for (int i = 0; i < 4; i++) {
        const int r0 = rowB + mbase + i * 16 + group;
#pragma unroll
        for (int j = 0; j < 4; j++) {
            const int c = colB + nbase + j * 8 + qd * 2;
            const float b0 = bias[c], b1 = bias[c + 1];
#pragma unroll
            for (int half = 0; half < 2; half++) {
                const int r = r0 + half * 8;
                const float v0 = (acc[i][j][half * 2 + 0] + b0) * alpha;
                const float v1 = (acc[i][j][half * 2 + 1] + b1) * alpha;
                __nv_bfloat162 p;
                p.x = __float2bfloat16(v0);
                p.y = __float2bfloat16(v1);
                *(__nv_bfloat162*)&outB[(size_t)r * H_ + c] = p;
                *(uint16_t*)&out8[(size_t)r * H_ + c] = f8pair(v0, v1);
            }
        }
    }
}

// ---------------------------------------------------------------------------
// Fused scores, per (128-row q-tile, head):
//  pass 1 (e4m3 mma): row sums of exp2(S')  -> linv
//  pass 2 (bf16 mma): column sums of exp2(S')*linv -> cs
// grid (16, 64), 256 threads, 96768 B dynamic smem.
// ---------------------------------------------------------------------------
#define P8B 80    // fp8 smem row pitch (bytes)
#define PBE 72    // bf16 smem row pitch (elements)

__global__ __launch_bounds__(256)
void scores_fused()
{
    extern __shared__ __align__(16) char dsm[];
    uint8_t* sQ8 = (uint8_t*)dsm;                                  // 10240
    uint8_t* sK8[2] = { (uint8_t*)(dsm + 10240), (uint8_t*)(dsm + 20480) };
    bf16* sQ = (bf16*)(dsm + 30720);                               // 18432
    bf16* sKb[2] = { (bf16*)(dsm + 49152), (bf16*)(dsm + 67584) };
    float* rs   = (float*)(dsm + 86016);                           // 2048
    float* linv = (float*)(dsm + 88064);                           // 512
    float* csp  = (float*)(dsm + 88576);                           // 8192

    const int tid = threadIdx.x;
    const int warp = tid >> 5, lane = tid & 31;
    const int wm = warp >> 2, wn = warp & 3;
    const int mbase = wm * 64, nbase = wn * 32;
    const int group = lane >> 2, qd = lane & 3;
    const int head = blockIdx.y;
    const int b = head >> 4, nh = head & 15;
    const int qB = blockIdx.x * 128;

    auto loadK8 = [&](int s, int kt) {
#pragma unroll
        for (int it = 0; it < 2; it++) {
            int ch = tid + it * 256;        // 512 chunks of 16B
            int row = ch >> 2, off = (ch & 3) * 16;
            cp16(smem_u32(&sK8[s][row * P8B + off]),
                 &g_K8[(size_t)(b * L_ + kt * 128 + row) * H_ + nh * 64 + off]);
        }
        CP_COMMIT();
    };
    auto loadKb = [&](int s, int kt) {
#pragma unroll
        for (int it = 0; it < 4; it++) {
            int ch = tid + it * 256;        // 1024 chunks of 16B
            int row = ch >> 3, off = (ch & 7) * 8;   // bf16 elems
            cp16(smem_u32(&sKb[s][row * PBE + off]),
                 &g_Kb[(size_t)(b * L_ + kt * 128 + row) * H_ + nh * 64 + off]);
        }
        CP_COMMIT();
    };

    // initial group: Q8 + Q bf16 + K8 tile 0
    {
#pragma unroll
        for (int it = 0; it < 2; it++) {
            int ch = tid + it * 256;
            int row = ch >> 2, off = (ch & 3) * 16;
            cp16(smem_u32(&sQ8[row * P8B + off]),
                 &g_Q8[(size_t)(b * L_ + qB + row) * H_ + nh * 64 + off]);
        }
#pragma unroll
        for (int it = 0; it < 4; it++) {
            int ch = tid + it * 256;
            int row = ch >> 3, off = (ch & 7) * 8;
            cp16(smem_u32(&sQ[row * PBE + off]),
                 &g_Qb[(size_t)(b * L_ + qB + row) * H_ + nh * 64 + off]);
        }
#pragma unroll
        for (int it = 0; it < 2; it++) {
            int ch = tid + it * 256;
            int row = ch >> 2, off = (ch & 3) * 16;
            cp16(smem_u32(&sK8[0][row * P8B + off]),
                 &g_K8[(size_t)(b * L_ + row) * H_ + nh * 64 + off]);
        }
        CP_COMMIT();
    }

    float acc[4][4][4];
    uint32_t af[4][4], bf[4][2];

    auto mma_tile8 = [&](const uint8_t* kbuf) {
#pragma unroll
        for (int i = 0; i < 4; i++)
#pragma unroll
            for (int j = 0; j < 4; j++)
#pragma unroll
                for (int p = 0; p < 4; p++) acc[i][j][p] = 0.f;
#pragma unroll
        for (int kk = 0; kk < 2; kk++) {    // two k=32 steps (32 bytes each)
#pragma unroll
            for (int i = 0; i < 4; i++)
                ldsm_x4(af[i][0], af[i][1], af[i][2], af[i][3],
                        smem_u32(&sQ8[(mbase + i * 16 + (lane & 15)) * P8B +
                                      kk * 32 + (lane >> 4) * 16]));
#pragma unroll
            for (int j = 0; j < 4; j++)
                ldsm_x2(bf[j][0], bf[j][1],
                        smem_u32(&kbuf[(nbase + j * 8 + (lane & 7)) * P8B +
                                       kk * 32 + ((lane >> 3) & 1) * 16]));
#pragma unroll
            for (int i = 0; i < 4; i++)
#pragma unroll
                for (int j = 0; j < 4; j++)
                    mma_fp8(acc[i][j], af[i], bf[j]);
        }
    };

    auto mma_tileb = [&](const bf16* kbuf) {
#pragma unroll
        for (int i = 0; i < 4; i++)
#pragma unroll
            for (int j = 0; j < 4; j++)
#pragma unroll
                for (int p = 0; p < 4; p++) acc[i][j][p] = 0.f;
#pragma unroll
        for (int kk = 0; kk < 64; kk += 16) {
#pragma unroll
            for (int i = 0; i < 4; i++)
                ldsm_x4(af[i][0], af[i][1], af[i][2], af[i][3],
                        smem_u32(&sQ[(mbase + i * 16 + (lane & 15)) * PBE +
                                     kk + (lane >> 4) * 8]));
#pragma unroll
            for (int j = 0; j < 4; j++)
                ldsm_x2(bf[j][0], bf[j][1],
                        smem_u32(&kbuf[(nbase + j * 8 + (lane & 7)) * PBE +
                                       kk + ((lane >> 3) & 1) * 8]));
#pragma unroll
            for (int i = 0; i < 4; i++)
#pragma unroll
                for (int j = 0; j < 4; j++)
                    mma_bf16(acc[i][j], af[i], bf[j]);
        }
    };

    // ---------------- pass 1 (fp8): row sums ----------------
    float racc[4][2];
#pragma unroll
    for (int i = 0; i < 4; i++) { racc[i][0] = 0.f; racc[i][1] = 0.f; }

    for (int kt = 0; kt < 16; kt++) {
        CP_WAIT0();
        __syncthreads();
        if (kt + 1 < 16) loadK8((kt + 1) & 1, kt + 1);
        mma_tile8(sK8[kt & 1]);
#pragma unroll
        for (int i = 0; i < 4; i++)
#pragma unroll
            for (int j = 0; j < 4; j++) {
                racc[i][0] += ex2f(acc[i][j][0]) + ex2f(acc[i][j][1]);
                racc[i][1] += ex2f(acc[i][j][2]) + ex2f(acc[i][j][3]);
            }
    }
    // prefetch first bf16 K tile while reducing
    loadKb(0, 0);

#pragma unroll
    for (int i = 0; i < 4; i++)
#pragma unroll
        for (int h = 0; h < 2; h++) {
            racc[i][h] += __shfl_xor_sync(0xFFFFFFFFu, racc[i][h], 1);
            racc[i][h] += __shfl_xor_sync(0xFFFFFFFFu, racc[i][h], 2);
        }
    if (qd == 0) {
#pragma unroll
        for (int i = 0; i < 4; i++)
#pragma unroll
            for (int h = 0; h < 2; h++)
                rs[(mbase + i * 16 + group + h * 8) * 4 + wn] = racc[i][h];
    }
    __syncthreads();
    if (tid < 128)
        linv[tid] = 1.f / (rs[tid * 4] + rs[tid * 4 + 1] + rs[tid * 4 + 2] + rs[tid * 4 + 3]);
#pragma unroll
    for (int t = 0; t < 8; t++) csp[tid + t * 256] = 0.f;
    __syncthreads();

    float li[4][2];
#pragma unroll
    for (int i = 0; i < 4; i++)
#pragma unroll
        for (int h = 0; h < 2; h++)
            li[i][h] = linv[mbase + i * 16 + group + h * 8];

    // ---------------- pass 2 (bf16): column sums ----------------
    for (int kt = 0; kt < 16; kt++) {
        CP_WAIT0();
        __syncthreads();
        if (kt + 1 < 16) loadKb((kt + 1) & 1, kt + 1);
        mma_tileb(sKb[kt & 1]);

        float colacc[8];
#pragma unroll
        for (int m = 0; m < 8; m++) colacc[m] = 0.f;
#pragma unroll
        for (int i = 0; i < 4; i++)
#pragma unroll
            for (int j = 0; j < 4; j++) {
                colacc[2 * j + 0] += ex2f(acc[i][j][0]) * li[i][0]
                                   + ex2f(acc[i][j][2]) * li[i][1];
                colacc[2 * j + 1] += ex2f(acc[i][j][1]) * li[i][0]
                                   + ex2f(acc[i][j][3]) * li[i][1];
            }
#pragma unroll
        for (int m = 0; m < 8; m++) {
            colacc[m] += __shfl_xor_sync(0xFFFFFFFFu, colacc[m], 4);
            colacc[m] += __shfl_xor_sync(0xFFFFFFFFu, colacc[m], 8);
            colacc[m] += __shfl_xor_sync(0xFFFFFFFFu, colacc[m], 16);
        }
        if (lane < 4) {
#pragma unroll
            for (int j = 0; j < 4; j++) {
                atomicAdd(&csp[kt * 128 + nbase + j * 8 + lane * 2 + 0], colacc[2 * j + 0]);
                atomicAdd(&csp[kt * 128 + nbase + j * 8 + lane * 2 + 1], colacc[2 * j + 1]);
            }
        }
    }
    __syncthreads();
#pragma unroll
    for (int t = 0; t < 8; t++)
        atomicAdd(&g_cs[head * L_ + tid + t * 256], csp[tid + t * 256]);
}

// ---------------------------------------------------------------------------
// wsum[head][h] = (1/L) sum_k cs[head,k] * x[b*L+k, h]   (fp32 exact)
// ---------------------------------------------------------------------------
__global__ __launch_bounds__(128)
void wsum_k(const float* __restrict__ x)
{
    __shared__ float scs[16][512];
    const int tid = threadIdx.x;
    const int h  = blockIdx.x * 128 + tid;
    const int b  = blockIdx.y;
    const int k0 = blockIdx.z * 512;

#pragma unroll
    for (int it = 0; it < 64; it++) {
        int w = tid + it * 128;
        scs[w >> 9][w & 511] = g_cs[(b * NH_ + (w >> 9)) * L_ + k0 + (w & 511)];
    }
    __syncthreads();

    float acc[16];
#pragma unroll
    for (int nh = 0; nh < NH_; nh++) acc[nh] = 0.f;

    const float* xp = x + (size_t)(b * L_ + k0) * H_ + h;
#pragma unroll 4
    for (int kk = 0; kk < 512; kk++) {
        float xv = xp[(size_t)kk * H_];
#pragma unroll
        for (int nh = 0; nh < NH_; nh++) acc[nh] += scs[nh][kk] * xv;
    }
#pragma unroll
    for (int nh = 0; nh < NH_; nh++)
        atomicAdd(&g_wsum[(b * NH_ + nh) * H_ + h], acc[nh] * (1.f / (float)L_));
}

// ---------------------------------------------------------------------------
__global__ __launch_bounds__(256)
void ctx_k(const float* __restrict__ Wv, const float* __restrict__ bv)
{
    __shared__ float sw[H_];
    const int tid = threadIdx.x;
    const int warp = tid >> 5, lane = tid & 31;
    const int head = blockIdx.x;
    const int b = head >> 4, nh = head & 15;

#pragma unroll
    for (int it = 0; it < 4; it++)
        sw[tid + it * 256] = g_wsum[head * H_ + tid + it * 256];
    __syncthreads();

#pragma unroll
    for (int d = 0; d < 8; d++) {
        const int dk = warp * 8 + d;
        const float* wr = Wv + (size_t)(nh * 64 + dk) * H_;
        float acc = 0.f;
#pragma unroll 8
        for (int h = lane; h < H_; h += 32) acc += sw[h] * wr[h];
#pragma unroll
        for (int off = 16; off > 0; off >>= 1)
            acc += __shfl_xor_sync(0xFFFFFFFFu, acc, off);
        if (lane == 0)
            g_ctxmean[b * H_ + nh * 64 + dk] = acc + bv[nh * 64 + dk];
    }
}

// ---------------------------------------------------------------------------
__global__ __launch_bounds__(256)
void pooled_kernel(const float* __restrict__ Wo, const float* __restrict__ bo,
                   float* __restrict__ out)
{
    const int warp = threadIdx.x >> 5;
    const int lane = threadIdx.x & 31;
    const int idx = blockIdx.x * 8 + warp;
    const int b = idx >> 10;
    const int o = idx & 1023;

    const float* cm = g_ctxmean + b * H_;
    const float* wr = Wo + (size_t)o * H_;
    float acc = 0.f;
#pragma unroll
    for (int h = lane; h < H_; h += 32) acc += cm[h] * wr[h];
#pragma unroll
    for (int off = 16; off > 0; off >>= 1)
        acc += __shfl_xor_sync(0xFFFFFFFFu, acc, off);
    if (lane == 0) out[idx] = acc + bo[o];
}

// ---------------------------------------------------------------------------
__global__ void weights_kernel(float* __restrict__ out)
{
    int i = blockIdx.x * blockDim.x + threadIdx.x;
    if (i >= B_ * L_) return;
    int b = i >> 11;
    int k = i & (L_ - 1);
    float s = 0.f;
#pragma unroll
    for (int nh = 0; nh < NH_; nh++)
        s += g_cs[(b * NH_ + nh) * L_ + k];
    out[B_ * H_ + i] = s * (1.f / (float)(NH_ * L_));
}

// ---------------------------------------------------------------------------
extern "C" void kernel_launch(void* const* d_in, const int* in_sizes, int n_in,
                              void* d_out, int out_size)
{
    const float* x  = (const float*)d_in[0];
    const float* Wq = (const float*)d_in[1];
    const float* bq = (const float*)d_in[2];
    const float* Wk = (const float*)d_in[3];
    const float* bk = (const float*)d_in[4];
    const float* Wv = (const float*)d_in[5];
    const float* bv = (const float*)d_in[6];
    const float* Wo = (const float*)d_in[7];
    const float* bo = (const float*)d_in[8];
    float* out = (float*)d_out;

    bf16 *dXhi, *dWqh, *dWkh;
    cudaGetSymbolAddress((void**)&dXhi, g_Xhi);
    cudaGetSymbolAddress((void**)&dWqh, g_Wqh);
    cudaGetSymbolAddress((void**)&dWkh, g_Wkh);

    cudaFuncSetAttribute(scores_fused, cudaFuncAttributeMaxDynamicSharedMemorySize, 96768);

    split_k<<<(ROWS_ * H_) / 256, 256>>>(x,  dXhi, ROWS_ * H_);
    split_k<<<(H_ * H_) / 256, 256>>>(Wq, dWqh, H_ * H_);
    split_k<<<(H_ * H_) / 256, 256>>>(Wk, dWkh, H_ * H_);
    zero_k<<<(HEADS_ * L_) / 256, 256>>>();

    gemm_qk<<<dim3(H_ / 128, ROWS_ / 128, 2), 256>>>(dXhi, dWqh, dWkh, bq, bk);

    scores_fused<<<dim3(L_ / 128, HEADS_), 256, 96768>>>();

    wsum_k<<<dim3(8, B_, 4), 128>>>(x);
    ctx_k<<<HEADS_, 256>>>(Wv, bv);
    pooled_kernel<<<512, 256>>>(Wo, bo, out);
    weights_kernel<<<(B_ * L_ + 255) / 256, 256>>>(out);
}

// round 6
// speedup vs baseline: 1.1684x; 1.1684x over previous
#include <cuda_runtime.h>
#include <cuda_bf16.h>
#include <cstdint>

#define B_  4
#define L_  2048
#define H_  1024
#define NH_ 16
#define DK_ 64
#define ROWS_ (B_ * L_)          // 8192
#define HEADS_ (B_ * NH_)        // 64
#define NROWS_ (HEADS_ * L_)     // 131072

typedef __nv_bfloat16 bf16;

// Q pre-scale: (1/sqrt(64)) * log2(e) -> scores in log2 domain, use ex2
#define QSCALE 0.18033688011112427f

// ---- scratch (device globals; allocation-free rule) ----
__device__ bf16    g_Xhi[ROWS_ * H_];
__device__ bf16    g_Wqh[H_ * H_];
__device__ bf16    g_Wkh[H_ * H_];
__device__ bf16    g_Qb[ROWS_ * H_];
__device__ bf16    g_Kb[ROWS_ * H_];
// E = exp2(S'), unnormalized, bf16 pairs in MMA-fragment micro-tile layout:
// [head][qt16][kt16][rg16][cg16][group8][qd4] (u32 = bf16x2)
__device__ uint32_t g_E32[(size_t)HEADS_ * 16 * 16 * 8192];  // 512MB
__device__ float   g_linv[NROWS_];
__device__ float   g_cs[HEADS_ * L_];
__device__ float   g_wsum[HEADS_ * H_];
__device__ float   g_ctxmean[B_ * H_];

// ---------------------------------------------------------------------------
// PTX helpers
// ---------------------------------------------------------------------------
__device__ __forceinline__ uint32_t smem_u32(const void* p) {
    return (uint32_t)__cvta_generic_to_shared(p);
}
__device__ __forceinline__ void ldsm_x4(uint32_t& r0, uint32_t& r1, uint32_t& r2,
                                        uint32_t& r3, uint32_t a) {
    asm volatile("ldmatrix.sync.aligned.m8n8.x4.shared.b16 {%0,%1,%2,%3}, [%4];"
                 : "=r"(r0), "=r"(r1), "=r"(r2), "=r"(r3) : "r"(a));
}
__device__ __forceinline__ void ldsm_x2(uint32_t& r0, uint32_t& r1, uint32_t a) {
    asm volatile("ldmatrix.sync.aligned.m8n8.x2.shared.b16 {%0,%1}, [%2];"
                 : "=r"(r0), "=r"(r1) : "r"(a));
}
__device__ __forceinline__ void mma_bf16(float* c, const uint32_t* a, const uint32_t* b) {
    asm volatile("mma.sync.aligned.m16n8k16.row.col.f32.bf16.bf16.f32 "
                 "{%0,%1,%2,%3}, {%4,%5,%6,%7}, {%8,%9}, {%0,%1,%2,%3};"
                 : "+f"(c[0]), "+f"(c[1]), "+f"(c[2]), "+f"(c[3])
                 : "r"(a[0]), "r"(a[1]), "r"(a[2]), "r"(a[3]), "r"(b[0]), "r"(b[1]));
}
__device__ __forceinline__ void cp16(uint32_t dst, const void* src) {
    asm volatile("cp.async.cg.shared.global [%0], [%1], 16;" :: "r"(dst), "l"(src));
}
#define CP_COMMIT()  asm volatile("cp.async.commit_group;" ::: "memory")
#define CP_WAIT0()   asm volatile("cp.async.wait_group 0;" ::: "memory")
#define CP_WAIT1()   asm volatile("cp.async.wait_group 1;" ::: "memory")

__device__ __forceinline__ float ex2f(float x) {
    float y;
    asm("ex2.approx.ftz.f32 %0, %1;" : "=f"(y) : "f"(x));
    return y;
}

// ---------------------------------------------------------------------------
// prep: x -> bf16
// ---------------------------------------------------------------------------
__global__ void split_x(const float* __restrict__ in, bf16* __restrict__ hi, int n)
{
    int i = blockIdx.x * blockDim.x + threadIdx.x;
    if (i >= n) return;
    hi[i] = __float2bfloat16(in[i]);
}

// prep: both weights -> bf16, zero wsum
__global__ void split_w(const float* __restrict__ Wq, const float* __restrict__ Wk)
{
    int i = blockIdx.x * blockDim.x + threadIdx.x;
    if (i < H_ * H_) {
        g_Wqh[i] = __float2bfloat16(Wq[i]);
        g_Wkh[i] = __float2bfloat16(Wk[i]);
    }
    if (i < HEADS_ * H_) g_wsum[i] = 0.f;
}

// ---------------------------------------------------------------------------
// Merged Q/K projection: z=0 -> Q (alpha=QSCALE), z=1 -> K.
// Y = X @ W^T + b, bf16 out row-major. 3-stage cp.async, BK=16.
// ---------------------------------------------------------------------------
__global__ __launch_bounds__(256)
void gemm_qk(const bf16* __restrict__ Xh,
             const float* __restrict__ bq, const float* __restrict__ bk)
{
    __shared__ bf16 sA[3][128][24];
    __shared__ bf16 sB[3][128][24];

    const int z = blockIdx.z;
    const bf16* Bh = z ? g_Kb /*placeholder*/ : nullptr;
    Bh = z ? g_Wkh : g_Wqh;
    const float* bias = z ? bk : bq;
    const float alpha = z ? 1.0f : QSCALE;
    bf16* outB = z ? g_Kb : g_Qb;

    const int tid = threadIdx.x;
    const int warp = tid >> 5, lane = tid & 31;
    const int wm = warp >> 2, wn = warp & 3;
    const int mbase = wm * 64, nbase = wn * 32;
    const int rowB = blockIdx.y * 128;
    const int colB = blockIdx.x * 128;

    float acc[4][4][4];
#pragma unroll
    for (int i = 0; i < 4; i++)
#pragma unroll
        for (int j = 0; j < 4; j++)
#pragma unroll
            for (int p = 0; p < 4; p++) acc[i][j][p] = 0.f;

    const int lrow = tid >> 1;
    const int lcb  = (tid & 1) * 8;

    auto load_stage = [&](int s, int t) {
        int k0 = t * 16;
        cp16(smem_u32(&sA[s][lrow][lcb]), Xh + (size_t)(rowB + lrow) * H_ + k0 + lcb);
        cp16(smem_u32(&sB[s][lrow][lcb]), Bh + (size_t)(colB + lrow) * H_ + k0 + lcb);
        CP_COMMIT();
    };

    load_stage(0, 0);
    load_stage(1, 1);

    const int T = H_ / 16;   // 64
    for (int t = 0; t < T; t++) {
        if (t + 1 < T) CP_WAIT1(); else CP_WAIT0();
        __syncthreads();
        if (t + 2 < T) load_stage((t + 2) % 3, t + 2);

        const int s = t % 3;
        uint32_t ah[4][4], bh[4][2];
#pragma unroll
        for (int i = 0; i < 4; i++)
            ldsm_x4(ah[i][0], ah[i][1], ah[i][2], ah[i][3],
                    smem_u32(&sA[s][mbase + i * 16 + (lane & 15)][(lane >> 4) * 8]));
#pragma unroll
        for (int j = 0; j < 4; j++)
            ldsm_x2(bh[j][0], bh[j][1],
                    smem_u32(&sB[s][nbase + j * 8 + (lane & 7)][((lane >> 3) & 1) * 8]));
#pragma unroll
        for (int i = 0; i < 4; i++)
#pragma unroll
            for (int j = 0; j < 4; j++)
                mma_bf16(acc[i][j], ah[i], bh[j]);
        __syncthreads();
    }

    const int group = lane >> 2, qd = lane & 3;
#pragma unroll
    for (int i = 0; i < 4; i++) {
        const int r0 = rowB + mbase + i * 16 + group;
#pragma unroll
        for (int j = 0; j < 4; j++) {
            const int c = colB + nbase + j * 8 + qd * 2;
            const float b0 = bias[c], b1 = bias[c + 1];
#pragma unroll
            for (int half = 0; half < 2; half++) {
                const int r = r0 + half * 8;
                __nv_bfloat162 p;
                p.x = __float2bfloat16((acc[i][j][half * 2 + 0] + b0) * alpha);
                p.y = __float2bfloat16((acc[i][j][half * 2 + 1] + b1) * alpha);
                *(__nv_bfloat162*)&outB[(size_t)r * H_ + c] = p;
            }
        }
    }
}

// ---------------------------------------------------------------------------
// Scores (single pass): per (q-tile 128, head), loop 16 K-tiles:
//   S' = Q K^T (bf16 mma), E = exp2(S') -> tiled g_E32 (coalesced 128B lines),
//   exact row sums -> g_linv (CTA-owned, no atomics).
// grid (16, 64), 256 threads. dyn smem 57344+2048.
// ---------------------------------------------------------------------------
#define PBE 72    // bf16 smem row pitch (elements)

__global__ __launch_bounds__(256)
void scores_store()
{
    extern __shared__ __align__(16) char dsm[];
    bf16* sQ = (bf16*)dsm;                                   // 18432
    bf16* sK[2] = { (bf16*)(dsm + 18432), (bf16*)(dsm + 36864) };
    float* rs = (float*)(dsm + 55296);                       // 128*4*4 = 2048

    const int tid = threadIdx.x;
    const int warp = tid >> 5, lane = tid & 31;
    const int wm = warp >> 2, wn = warp & 3;
    const int mbase = wm * 64, nbase = wn * 32;
    const int group = lane >> 2, qd = lane & 3;
    const int head = blockIdx.y;
    const int b = head >> 4, nh = head & 15;
    const int qt = blockIdx.x;
    const int qB = qt * 128;

    // load Q tile
#pragma unroll
    for (int it = 0; it < 4; it++) {
        int idx = tid + it * 256;
        int row = idx >> 3, col = (idx & 7) * 8;
        cp16(smem_u32(&sQ[row * PBE + col]),
             &g_Qb[(size_t)(b * L_ + qB + row) * H_ + nh * 64 + col]);
    }
    auto loadK = [&](int s, int kt) {
#pragma unroll
        for (int it = 0; it < 4; it++) {
            int idx = tid + it * 256;
            int row = idx >> 3, col = (idx & 7) * 8;
            cp16(smem_u32(&sK[s][row * PBE + col]),
                 &g_Kb[(size_t)(b * L_ + kt * 128 + row) * H_ + nh * 64 + col]);
        }
        CP_COMMIT();
    };
    loadK(0, 0);

    float racc[4][2];
#pragma unroll
    for (int i = 0; i < 4; i++) { racc[i][0] = 0.f; racc[i][1] = 0.f; }

    const size_t headbase = ((size_t)head * 16 + qt) * 16;   // tile units

    for (int kt = 0; kt < 16; kt++) {
        CP_WAIT0();
        __syncthreads();
        if (kt + 1 < 16) loadK((kt + 1) & 1, kt + 1);

        float acc[4][4][4];
        uint32_t ah[4][4], bh[4][2];
#pragma unroll
        for (int i = 0; i < 4; i++)
#pragma unroll
            for (int j = 0; j < 4; j++)
#pragma unroll
                for (int p = 0; p < 4; p++) acc[i][j][p] = 0.f;

        const bf16* kbuf = sK[kt & 1];
#pragma unroll
        for (int kk = 0; kk < 64; kk += 16) {
#pragma unroll
            for (int i = 0; i < 4; i++)
                ldsm_x4(ah[i][0], ah[i][1], ah[i][2], ah[i][3],
                        smem_u32(&sQ[(mbase + i * 16 + (lane & 15)) * PBE +
                                     kk + (lane >> 4) * 8]));
#pragma unroll
            for (int j = 0; j < 4; j++)
                ldsm_x2(bh[j][0], bh[j][1],
                        smem_u32(&kbuf[(nbase + j * 8 + (lane & 7)) * PBE +
                                       kk + ((lane >> 3) & 1) * 8]));
#pragma unroll
            for (int i = 0; i < 4; i++)
#pragma unroll
                for (int j = 0; j < 4; j++)
                    mma_bf16(acc[i][j], ah[i], bh[j]);
        }

        // epilogue: exp2, rowsum, tiled store (warp-coalesced 128B lines)
        uint32_t* tb = g_E32 + (headbase + kt) * 8192;
#pragma unroll
        for (int i = 0; i < 4; i++)
#pragma unroll
            for (int j = 0; j < 4; j++) {
                const int cg = wn * 4 + j;
#pragma unroll
                for (int half = 0; half < 2; half++) {
                    float e0 = ex2f(acc[i][j][half * 2 + 0]);
                    float e1 = ex2f(acc[i][j][half * 2 + 1]);
                    racc[i][half] += e0 + e1;
                    __nv_bfloat162 p;
                    p.x = __float2bfloat16(e0);
                    p.y = __float2bfloat16(e1);
                    const int rg = wm * 8 + i * 2 + half;
                    tb[((rg * 16 + cg) * 8 + group) * 4 + qd] = *(uint32_t*)&p;
                }
            }
    }

    // row-sum reduction -> linv (global, CTA-owned rows)
#pragma unroll
    for (int i = 0; i < 4; i++)
#pragma unroll
        for (int h = 0; h < 2; h++) {
            racc[i][h] += __shfl_xor_sync(0xFFFFFFFFu, racc[i][h], 1);
            racc[i][h] += __shfl_xor_sync(0xFFFFFFFFu, racc[i][h], 2);
        }
    if (qd == 0) {
#pragma unroll
        for (int i = 0; i < 4; i++)
#pragma unroll
            for (int h = 0; h < 2; h++)
                rs[(mbase + i * 16 + group + h * 8) * 4 + wn] = racc[i][h];
    }
    __syncthreads();
    if (tid < 128)
        g_linv[head * L_ + qB + tid] =
            1.f / (rs[tid * 4] + rs[tid * 4 + 1] + rs[tid * 4 + 2] + rs[tid * 4 + 3]);
}

// ---------------------------------------------------------------------------
// Colsum stream: cs[head][col] = sum_q E[q][col] * linv[q]
// grid (16 kt, 64 head), 256 threads. Pure streaming, no atomics.
// ---------------------------------------------------------------------------
__global__ __launch_bounds__(256)
void colsum_tiled()
{
    __shared__ float s_li[L_];
    const int tid = threadIdx.x;
    const int w = tid >> 5, lane = tid & 31;
    const int g = lane >> 2, qd = lane & 3;
    const int kt = blockIdx.x;
    const int head = blockIdx.y;

#pragma unroll
    for (int it = 0; it < 8; it++)
        s_li[tid + it * 256] = g_linv[head * L_ + tid + it * 256];
    __syncthreads();

    float a0x = 0.f, a0y = 0.f, a1x = 0.f, a1y = 0.f;

    for (int qt = 0; qt < 16; qt++) {
        const uint32_t* tb = g_E32 + (((size_t)head * 16 + qt) * 16 + kt) * 8192;
        const float* lip = s_li + qt * 128;
#pragma unroll 4
        for (int rg = 0; rg < 16; rg++) {
            const int row = (rg >> 3) * 64 + ((rg >> 1) & 3) * 16 + (rg & 1) * 8 + g;
            const float li = lip[row];
            const uint32_t v0 = tb[((rg * 16 + w * 2 + 0) * 8 + g) * 4 + qd];
            const uint32_t v1 = tb[((rg * 16 + w * 2 + 1) * 8 + g) * 4 + qd];
            a0x += __uint_as_float(v0 << 16) * li;
            a0y += __uint_as_float(v0 & 0xFFFF0000u) * li;
            a1x += __uint_as_float(v1 << 16) * li;
            a1y += __uint_as_float(v1 & 0xFFFF0000u) * li;
        }
    }

    // reduce over group lanes (stride 4,8,16)
#pragma unroll
    for (int off = 4; off <= 16; off <<= 1) {
        a0x += __shfl_xor_sync(0xFFFFFFFFu, a0x, off);
        a0y += __shfl_xor_sync(0xFFFFFFFFu, a0y, off);
        a1x += __shfl_xor_sync(0xFFFFFFFFu, a1x, off);
        a1y += __shfl_xor_sync(0xFFFFFFFFu, a1y, off);
    }
    if (lane < 4) {
        const int col0 = kt * 128 + (w * 2 + 0) * 8 + qd * 2;
        const int col1 = kt * 128 + (w * 2 + 1) * 8 + qd * 2;
        *(float2*)&g_cs[head * L_ + col0] = make_float2(a0x, a0y);
        *(float2*)&g_cs[head * L_ + col1] = make_float2(a1x, a1y);
    }
}

// ---------------------------------------------------------------------------
// wsum[head][h] = (1/L) sum_k cs[head,k] * x[b*L+k, h]   (fp32 exact)
// ---------------------------------------------------------------------------
__global__ __launch_bounds__(128)
void wsum_k(const float* __restrict__ x)
{
    __shared__ float scs[16][512];
    const int tid = threadIdx.x;
    const int h  = blockIdx.x * 128 + tid;
    const int b  = blockIdx.y;
    const int k0 = blockIdx.z * 512;

#pragma unroll
    for (int it = 0; it < 64; it++) {
        int w = tid + it * 128;
        scs[w >> 9][w & 511] = g_cs[(b * NH_ + (w >> 9)) * L_ + k0 + (w & 511)];
    }
    __syncthreads();

    float acc[16];
#pragma unroll
    for (int nh = 0; nh < NH_; nh++) acc[nh] = 0.f;

    const float* xp = x + (size_t)(b * L_ + k0) * H_ + h;
#pragma unroll 4
    for (int kk = 0; kk < 512; kk++) {
        float xv = xp[(size_t)kk * H_];
#pragma unroll
        for (int nh = 0; nh < NH_; nh++) acc[nh] += scs[nh][kk] * xv;
    }
#pragma unroll
    for (int nh = 0; nh < NH_; nh++)
        atomicAdd(&g_wsum[(b * NH_ + nh) * H_ + h], acc[nh] * (1.f / (float)L_));
}

// ---------------------------------------------------------------------------
__global__ __launch_bounds__(256)
void ctx_k(const float* __restrict__ Wv, const float* __restrict__ bv)
{
    __shared__ float sw[H_];
    const int tid = threadIdx.x;
    const int warp = tid >> 5, lane = tid & 31;
    const int head = blockIdx.x;
    const int b = head >> 4, nh = head & 15;

#pragma unroll
    for (int it = 0; it < 4; it++)
        sw[tid + it * 256] = g_wsum[head * H_ + tid + it * 256];
    __syncthreads();

#pragma unroll
    for (int d = 0; d < 8; d++) {
        const int dk = warp * 8 + d;
        const float* wr = Wv + (size_t)(nh * 64 + dk) * H_;
        float acc = 0.f;
#pragma unroll 8
        for (int h = lane; h < H_; h += 32) acc += sw[h] * wr[h];
#pragma unroll
        for (int off = 16; off > 0; off >>= 1)
            acc += __shfl_xor_sync(0xFFFFFFFFu, acc, off);
        if (lane == 0)
            g_ctxmean[b * H_ + nh * 64 + dk] = acc + bv[nh * 64 + dk];
    }
}

// ---------------------------------------------------------------------------
__global__ __launch_bounds__(256)
void pooled_kernel(const float* __restrict__ Wo, const float* __restrict__ bo,
                   float* __restrict__ out)
{
    const int warp = threadIdx.x >> 5;
    const int lane = threadIdx.x & 31;
    const int idx = blockIdx.x * 8 + warp;
    const int b = idx >> 10;
    const int o = idx & 1023;

    const float* cm = g_ctxmean + b * H_;
    const float* wr = Wo + (size_t)o * H_;
    float acc = 0.f;
#pragma unroll
    for (int h = lane; h < H_; h += 32) acc += cm[h] * wr[h];
#pragma unroll
    for (int off = 16; off > 0; off >>= 1)
        acc += __shfl_xor_sync(0xFFFFFFFFu, acc, off);
    if (lane == 0) out[idx] = acc + bo[o];
}

// ---------------------------------------------------------------------------
__global__ void weights_kernel(float* __restrict__ out)
{
    int i = blockIdx.x * blockDim.x + threadIdx.x;
    if (i >= B_ * L_) return;
    int b = i >> 11;
    int k = i & (L_ - 1);
    float s = 0.f;
#pragma unroll
    for (int nh = 0; nh < NH_; nh++)
        s += g_cs[(b * NH_ + nh) * L_ + k];
    out[B_ * H_ + i] = s * (1.f / (float)(NH_ * L_));
}

// ---------------------------------------------------------------------------
extern "C" void kernel_launch(void* const* d_in, const int* in_sizes, int n_in,
                              void* d_out, int out_size)
{
    const float* x  = (const float*)d_in[0];
    const float* Wq = (const float*)d_in[1];
    const float* bq = (const float*)d_in[2];
    const float* Wk = (const float*)d_in[3];
    const float* bk = (const float*)d_in[4];
    const float* Wv = (const float*)d_in[5];
    const float* bv = (const float*)d_in[6];
    const float* Wo = (const float*)d_in[7];
    const float* bo = (const float*)d_in[8];
    float* out = (float*)d_out;

    bf16* dXhi;
    cudaGetSymbolAddress((void**)&dXhi, g_Xhi);

    cudaFuncSetAttribute(scores_store, cudaFuncAttributeMaxDynamicSharedMemorySize, 57344);

    split_x<<<(ROWS_ * H_) / 256, 256>>>(x, dXhi, ROWS_ * H_);
    split_w<<<(H_ * H_) / 256, 256>>>(Wq, Wk);

    gemm_qk<<<dim3(H_ / 128, ROWS_ / 128, 2), 256>>>(dXhi, bq, bk);

    scores_store<<<dim3(16, HEADS_), 256, 57344>>>();
    colsum_tiled<<<dim3(16, HEADS_), 256>>>();

    wsum_k<<<dim3(8, B_, 4), 128>>>(x);
    ctx_k<<<HEADS_, 256>>>(Wv, bv);
    pooled_kernel<<<512, 256>>>(Wo, bo, out);
    weights_kernel<<<(B_ * L_ + 255) / 256, 256>>>(out);
}